// round 4
// baseline (speedup 1.0000x reference)
#include <cuda_runtime.h>
#include <math.h>

#define Bb 8
#define Nn 784
#define Cc 768
#define Hh 8
#define Dd 96
#define NM 614656               /* 784*784 */
#define QK_SCALE 0.10206207261596577f  /* 96^-0.5 */
#define BN_CNT 4917248.0        /* B*NM */

/* ------------- static scratch (no allocation allowed) ------------- */
__device__ float  g_qh[Bb*Hh*Nn*Dd];
__device__ float  g_kh[Bb*Hh*Nn*Dd];
__device__ float  g_vh[Bb*Hh*Nn*Dd];
__device__ float  g_P[(size_t)Bb*Hh*NM];   /* scores -> probs -> mixed attn (in place) */
__device__ float  g_X[Bb*Nn*Cc];           /* attn @ V, (b,n,c) */
__device__ double g_stats[16];             /* sum[8], sumsq[8] */
__device__ float  g_st[16];                /* scale[8], shift[8] */

/* ------------------- packed f32x2 FMA helpers --------------------- */
__device__ __forceinline__ unsigned long long f2pk(float lo, float hi){
    unsigned long long r;
    asm("mov.b64 %0, {%1, %2};" : "=l"(r) : "f"(lo), "f"(hi));
    return r;
}
__device__ __forceinline__ void f2fma(unsigned long long& d,
                                      unsigned long long a,
                                      unsigned long long b){
    asm("fma.rn.f32x2 %0, %1, %2, %0;" : "+l"(d) : "l"(a), "l"(b));
}
__device__ __forceinline__ float2 f2up(unsigned long long v){
    float2 r;
    asm("mov.b64 {%0, %1}, %2;" : "=f"(r.x), "=f"(r.y) : "l"(v));
    return r;
}

/* K0: zero stats */
__global__ void k_zero(){
    if(threadIdx.x < 16) g_stats[threadIdx.x] = 0.0;
}

/* K1: 3x3 same-pad conv per token; grid (B*N, 3), block 256.
   Q path output is pre-scaled by QK_SCALE. */
__global__ void k_conv(const float* __restrict__ q,
                       const float* __restrict__ kk,
                       const float* __restrict__ vv,
                       const float* __restrict__ Wq,
                       const float* __restrict__ Wk,
                       const float* __restrict__ Wv){
    const int bn = blockIdx.x;
    const int which = blockIdx.y;
    const float* x = (which==0 ? q : (which==1 ? kk : vv)) + (size_t)bn*Cc;
    const float* W = (which==0 ? Wq : (which==1 ? Wk : Wv));
    float* out = (which==0 ? g_qh : (which==1 ? g_kh : g_vh));
    const float post = (which==0 ? QK_SCALE : 1.0f);

    __shared__ float xs[768];
    __shared__ float ws[81];
    const int t = threadIdx.x;
    xs[t]       = x[t];
    xs[t + 256] = x[t + 256];
    xs[t + 512] = x[t + 512];
    if(t < 81) ws[t] = W[t];
    __syncthreads();

    const int i = t >> 4, j = t & 15;
    const int b = bn / Nn, n = bn % Nn;
    #pragma unroll
    for(int o = 0; o < 3; o++){
        float acc = 0.f;
        #pragma unroll
        for(int c = 0; c < 3; c++){
            const float* xp = xs + c*256;
            const float* wp = ws + (o*3 + c)*9;
            #pragma unroll
            for(int di = 0; di < 3; di++){
                int ii = i + di - 1;
                if(ii < 0 || ii > 15) continue;
                #pragma unroll
                for(int dj = 0; dj < 3; dj++){
                    int jj = j + dj - 1;
                    if(jj < 0 || jj > 15) continue;
                    acc = fmaf(wp[di*3 + dj], xp[ii*16 + jj], acc);
                }
            }
        }
        const int idx = o*256 + i*16 + j;
        const int h = idx / Dd, d = idx % Dd;
        out[(((size_t)b*Hh + h)*Nn + n)*Dd + d] = acc * post;
    }
}

/* K2: S = Q_scaled K^T ; grid (7,7,64), block 256, 128x128 tile */
__global__ __launch_bounds__(256) void k_qk(){
    const int bh = blockIdx.z;
    const int m0 = blockIdx.x*128, n0 = blockIdx.y*128;
    const float* __restrict__ Ag = g_qh + (size_t)bh*Nn*Dd;
    const float* __restrict__ Bg = g_kh + (size_t)bh*Nn*Dd;
    __shared__ float As[16][132];
    __shared__ float Bs[16][132];
    const int tid = threadIdx.x;
    const int tx = tid & 15, ty = tid >> 4;

    unsigned long long acc[8][4];
    #pragma unroll
    for(int r=0;r<8;r++)
        #pragma unroll
        for(int c=0;c<4;c++) acc[r][c]=0ULL;

    for(int k0 = 0; k0 < Dd; k0 += 16){
        #pragma unroll
        for(int it = 0; it < 2; it++){
            int idx = tid + it*256;           /* 0..511 */
            int r = idx >> 2, kq = idx & 3;
            float4 va = make_float4(0.f,0.f,0.f,0.f);
            float4 vb = make_float4(0.f,0.f,0.f,0.f);
            if(n0 + r < Nn) va = *(const float4*)(Ag + (size_t)(n0+r)*Dd + k0 + kq*4);
            if(m0 + r < Nn) vb = *(const float4*)(Bg + (size_t)(m0+r)*Dd + k0 + kq*4);
            As[kq*4+0][r]=va.x; As[kq*4+1][r]=va.y; As[kq*4+2][r]=va.z; As[kq*4+3][r]=va.w;
            Bs[kq*4+0][r]=vb.x; Bs[kq*4+1][r]=vb.y; Bs[kq*4+2][r]=vb.z; Bs[kq*4+3][r]=vb.w;
        }
        __syncthreads();
        #pragma unroll
        for(int k = 0; k < 16; k++){
            float4 a0 = *(const float4*)&As[k][ty*8];
            float4 a1 = *(const float4*)&As[k][ty*8+4];
            float4 b0 = *(const float4*)&Bs[k][tx*8];
            float4 b1 = *(const float4*)&Bs[k][tx*8+4];
            unsigned long long bp0 = f2pk(b0.x,b0.y), bp1 = f2pk(b0.z,b0.w);
            unsigned long long bp2 = f2pk(b1.x,b1.y), bp3 = f2pk(b1.z,b1.w);
            float av[8] = {a0.x,a0.y,a0.z,a0.w,a1.x,a1.y,a1.z,a1.w};
            #pragma unroll
            for(int r = 0; r < 8; r++){
                unsigned long long ad = f2pk(av[r], av[r]);
                f2fma(acc[r][0], ad, bp0);
                f2fma(acc[r][1], ad, bp1);
                f2fma(acc[r][2], ad, bp2);
                f2fma(acc[r][3], ad, bp3);
            }
        }
        __syncthreads();
    }

    float* __restrict__ C = g_P + (size_t)bh*NM;
    #pragma unroll
    for(int r = 0; r < 8; r++){
        int n = n0 + ty*8 + r;
        if(n >= Nn) continue;
        #pragma unroll
        for(int c = 0; c < 4; c++){
            float2 v = f2up(acc[r][c]);
            int m = m0 + tx*8 + c*2;
            if(m   < Nn) C[(size_t)n*Nn + m]   = v.x;
            if(m+1 < Nn) C[(size_t)n*Nn + m+1] = v.y;
        }
    }
}

/* K3: in-place row softmax; grid (64*784), block 256 */
__global__ __launch_bounds__(256) void k_softmax(){
    float* __restrict__ row = g_P + (size_t)blockIdx.x * Nn;
    const int tid = threadIdx.x;
    const int lane = tid & 31, wid = tid >> 5;
    __shared__ float red[8];
    __shared__ float bc;

    float v[4];
    #pragma unroll
    for(int i = 0; i < 4; i++){
        int j = tid + i*256;
        v[i] = (j < Nn) ? row[j] : -1e30f;
    }
    float mx = fmaxf(fmaxf(v[0],v[1]), fmaxf(v[2],v[3]));
    #pragma unroll
    for(int o = 16; o > 0; o >>= 1) mx = fmaxf(mx, __shfl_xor_sync(0xffffffffu, mx, o));
    if(lane == 0) red[wid] = mx;
    __syncthreads();
    if(tid == 0){
        float m = red[0];
        #pragma unroll
        for(int w = 1; w < 8; w++) m = fmaxf(m, red[w]);
        bc = m;
    }
    __syncthreads();
    mx = bc;

    float s = 0.f;
    #pragma unroll
    for(int i = 0; i < 4; i++){
        int j = tid + i*256;
        v[i] = (j < Nn) ? __expf(v[i] - mx) : 0.f;
        s += v[i];
    }
    #pragma unroll
    for(int o = 16; o > 0; o >>= 1) s += __shfl_xor_sync(0xffffffffu, s, o);
    __syncthreads();
    if(lane == 0) red[wid] = s;
    __syncthreads();
    if(tid == 0){
        float t = 0.f;
        #pragma unroll
        for(int w = 0; w < 8; w++) t += red[w];
        bc = 1.f / t;
    }
    __syncthreads();
    float inv = bc;
    #pragma unroll
    for(int i = 0; i < 4; i++){
        int j = tid + i*256;
        if(j < Nn) row[j] = v[i] * inv;
    }
}

/* K4: cross-head mix IN PLACE on g_P + BN stats; grid (2401, 8), block 256.
   Each thread reads its element from all 8 head planes, computes all 8
   mixed outputs, writes back to the same locations. Thread-local -> safe. */
__global__ __launch_bounds__(256) void k_mix(const float* __restrict__ Wre,
                                             const float* __restrict__ bre){
    __shared__ float wsh[64];
    __shared__ float bsh[8];
    __shared__ float bsum[16];
    const int tid = threadIdx.x;
    const int lane = tid & 31;
    if(tid < 64) wsh[tid] = Wre[tid];
    if(tid < 8)  bsh[tid] = bre[tid];
    if(tid < 16) bsum[tid] = 0.f;
    __syncthreads();

    const int b = blockIdx.y;
    const size_t idx = (size_t)blockIdx.x*256 + tid;   /* < NM */
    float* __restrict__ Pp = g_P + (size_t)b*Hh*NM + idx;

    float p[8];
    #pragma unroll
    for(int h = 0; h < 8; h++) p[h] = Pp[(size_t)h*NM];

    float ls[8], lq[8];
    float av[8];
    #pragma unroll
    for(int o = 0; o < 8; o++){
        float a = bsh[o];
        #pragma unroll
        for(int h = 0; h < 8; h++) a = fmaf(wsh[o*8+h], p[h], a);
        av[o] = a;
        ls[o] = a;
        lq[o] = a*a;
    }
    #pragma unroll
    for(int o = 0; o < 8; o++) Pp[(size_t)o*NM] = av[o];

    #pragma unroll
    for(int o = 0; o < 8; o++){
        #pragma unroll
        for(int s = 16; s > 0; s >>= 1){
            ls[o] += __shfl_xor_sync(0xffffffffu, ls[o], s);
            lq[o] += __shfl_xor_sync(0xffffffffu, lq[o], s);
        }
    }
    if(lane == 0){
        #pragma unroll
        for(int o = 0; o < 8; o++){
            atomicAdd(&bsum[o],   ls[o]);
            atomicAdd(&bsum[8+o], lq[o]);
        }
    }
    __syncthreads();
    if(tid < 16) atomicAdd(&g_stats[tid], (double)bsum[tid]);
}

/* K5: finalize BN affine */
__global__ void k_bnfin(const float* __restrict__ gamma,
                        const float* __restrict__ beta){
    int o = threadIdx.x;
    if(o < 8){
        double mean = g_stats[o]   / BN_CNT;
        double var  = g_stats[8+o] / BN_CNT - mean*mean;
        float s = gamma[o] * rsqrtf((float)var + 1e-5f);
        g_st[o]   = s;
        g_st[8+o] = beta[o] - (float)mean * s;
    }
}

/* K6: X = BN(A) @ V ; grid (13, 64), block 256; tile 64 rows x 96 cols */
__global__ __launch_bounds__(256) void k_av(){
    const int bh = blockIdx.y;
    const int n0 = blockIdx.x * 64;
    const int o  = bh & 7;
    const int b  = bh >> 3;
    const float s = g_st[o];
    const float t = g_st[8+o];
    const float* __restrict__ Ag = g_P + (size_t)bh*NM;
    const float* __restrict__ Vg = g_vh + (size_t)bh*Nn*Dd;

    __shared__ float As2[64][36];
    __shared__ float Vs[32][100];
    const int tid = threadIdx.x;
    const int tx = tid & 15, ty = tid >> 4;

    unsigned long long acc[4][3];
    #pragma unroll
    for(int i=0;i<4;i++)
        #pragma unroll
        for(int j=0;j<3;j++) acc[i][j]=0ULL;

    for(int mc = 0; mc < Nn; mc += 32){
        /* A tile 64x32 with BN applied; zero for padded rows/cols */
        #pragma unroll
        for(int it = 0; it < 2; it++){
            int idx = tid + it*256;         /* 0..511 */
            int r = idx >> 3, kq = idx & 7;
            int m = mc + kq*4;
            float4 va = make_float4(0.f,0.f,0.f,0.f);
            if(n0 + r < Nn && m + 3 < Nn){
                float4 raw = *(const float4*)(Ag + (size_t)(n0+r)*Nn + m);
                va.x = fmaf(raw.x, s, t);
                va.y = fmaf(raw.y, s, t);
                va.z = fmaf(raw.z, s, t);
                va.w = fmaf(raw.w, s, t);
            }
            *(float4*)&As2[r][kq*4] = va;
        }
        /* V tile 32x96 */
        #pragma unroll
        for(int it = 0; it < 3; it++){
            int idx = tid + it*256;         /* 0..767 */
            int r = idx / 24, dq = idx % 24;
            float4 vv = make_float4(0.f,0.f,0.f,0.f);
            if(mc + r < Nn) vv = *(const float4*)(Vg + (size_t)(mc+r)*Dd + dq*4);
            *(float4*)&Vs[r][dq*4] = vv;
        }
        __syncthreads();
        #pragma unroll 4
        for(int k = 0; k < 32; k++){
            float2 b0 = *(const float2*)&Vs[k][tx*6];
            float2 b1 = *(const float2*)&Vs[k][tx*6+2];
            float2 b2 = *(const float2*)&Vs[k][tx*6+4];
            unsigned long long bp0 = f2pk(b0.x,b0.y);
            unsigned long long bp1 = f2pk(b1.x,b1.y);
            unsigned long long bp2 = f2pk(b2.x,b2.y);
            #pragma unroll
            for(int i = 0; i < 4; i++){
                float a = As2[ty*4+i][k];
                unsigned long long ad = f2pk(a, a);
                f2fma(acc[i][0], ad, bp0);
                f2fma(acc[i][1], ad, bp1);
                f2fma(acc[i][2], ad, bp2);
            }
        }
        __syncthreads();
    }

    #pragma unroll
    for(int i = 0; i < 4; i++){
        int n = n0 + ty*4 + i;
        if(n >= Nn) continue;
        float* outp = g_X + ((size_t)(b*Nn + n))*Cc + o*Dd + tx*6;
        #pragma unroll
        for(int j = 0; j < 3; j++){
            float2 v = f2up(acc[i][j]);
            outp[j*2]   = v.x;
            outp[j*2+1] = v.y;
        }
    }
}

/* K7: out = X @ Wp^T + bp ; grid (6, 49), block 256, 128x128 tile */
__global__ __launch_bounds__(256) void k_proj(float* __restrict__ out,
                                              const float* __restrict__ Wp,
                                              const float* __restrict__ bp){
    const int c0 = blockIdx.x*128, n0 = blockIdx.y*128;
    const float* __restrict__ Ag = g_X;
    __shared__ float As[16][132];
    __shared__ float Bs[16][132];
    const int tid = threadIdx.x;
    const int tx = tid & 15, ty = tid >> 4;

    unsigned long long acc[8][4];
    #pragma unroll
    for(int r=0;r<8;r++)
        #pragma unroll
        for(int c=0;c<4;c++) acc[r][c]=0ULL;

    for(int k0 = 0; k0 < Cc; k0 += 16){
        #pragma unroll
        for(int it = 0; it < 2; it++){
            int idx = tid + it*256;
            int r = idx >> 2, kq = idx & 3;
            float4 va = *(const float4*)(Ag + (size_t)(n0+r)*Cc + k0 + kq*4);
            float4 vb = *(const float4*)(Wp + (size_t)(c0+r)*Cc + k0 + kq*4);
            As[kq*4+0][r]=va.x; As[kq*4+1][r]=va.y; As[kq*4+2][r]=va.z; As[kq*4+3][r]=va.w;
            Bs[kq*4+0][r]=vb.x; Bs[kq*4+1][r]=vb.y; Bs[kq*4+2][r]=vb.z; Bs[kq*4+3][r]=vb.w;
        }
        __syncthreads();
        #pragma unroll
        for(int k = 0; k < 16; k++){
            float4 a0 = *(const float4*)&As[k][ty*8];
            float4 a1 = *(const float4*)&As[k][ty*8+4];
            float4 b0 = *(const float4*)&Bs[k][tx*8];
            float4 b1 = *(const float4*)&Bs[k][tx*8+4];
            unsigned long long bp0 = f2pk(b0.x,b0.y), bp1 = f2pk(b0.z,b0.w);
            unsigned long long bp2 = f2pk(b1.x,b1.y), bp3 = f2pk(b1.z,b1.w);
            float av[8] = {a0.x,a0.y,a0.z,a0.w,a1.x,a1.y,a1.z,a1.w};
            #pragma unroll
            for(int r = 0; r < 8; r++){
                unsigned long long ad = f2pk(av[r], av[r]);
                f2fma(acc[r][0], ad, bp0);
                f2fma(acc[r][1], ad, bp1);
                f2fma(acc[r][2], ad, bp2);
                f2fma(acc[r][3], ad, bp3);
            }
        }
        __syncthreads();
    }

    #pragma unroll
    for(int r = 0; r < 8; r++){
        int n = n0 + ty*8 + r;
        #pragma unroll
        for(int c = 0; c < 4; c++){
            float2 v = f2up(acc[r][c]);
            int cc = c0 + tx*8 + c*2;
            out[(size_t)n*Cc + cc]   = v.x + bp[cc];
            out[(size_t)n*Cc + cc+1] = v.y + bp[cc+1];
        }
    }
}

extern "C" void kernel_launch(void* const* d_in, const int* in_sizes, int n_in,
                              void* d_out, int out_size){
    const float* q    = (const float*)d_in[0];
    const float* k    = (const float*)d_in[1];
    const float* v    = (const float*)d_in[2];
    const float* Wq   = (const float*)d_in[3];
    const float* Wk   = (const float*)d_in[4];
    const float* Wv   = (const float*)d_in[5];
    const float* Wre  = (const float*)d_in[6];
    const float* bre  = (const float*)d_in[7];
    const float* gma  = (const float*)d_in[8];
    const float* beta = (const float*)d_in[9];
    const float* Wp   = (const float*)d_in[10];
    const float* bp   = (const float*)d_in[11];
    float* out = (float*)d_out;

    k_zero<<<1, 32>>>();
    k_conv<<<dim3(Bb*Nn, 3), 256>>>(q, k, v, Wq, Wk, Wv);
    k_qk<<<dim3(7, 7, Bb*Hh), 256>>>();
    k_softmax<<<Bb*Hh*Nn, 256>>>();
    k_mix<<<dim3(NM/256, Bb), 256>>>(Wre, bre);
    k_bnfin<<<1, 32>>>(gma, beta);
    k_av<<<dim3(13, Bb*Hh), 256>>>();
    k_proj<<<dim3(6, 49), 256>>>(out, Wp, bp);
}

// round 7
// speedup vs baseline: 1.0855x; 1.0855x over previous
#include <cuda_runtime.h>
#include <cuda_bf16.h>
#include <cstdint>
#include <math.h>

#define Bb 8
#define Nn 784
#define Cc 768
#define Hh 8
#define Dd 96
#define NM 614656               /* 784*784 */
#define QK_SCALE 0.10206207261596577f  /* 96^-0.5 */
#define BN_CNT 4917248.0        /* B*NM */
#define NPAIR 48                /* bf16 pairs per head row (96/2) */
#define CVT_PAIRS (Bb*Hh*Nn*NPAIR)   /* 2408448 */

/* ------------- static scratch (no allocation allowed) ------------- */
__device__ float  g_qh[Bb*Hh*Nn*Dd];
__device__ float  g_kh[Bb*Hh*Nn*Dd];
__device__ float  g_vh[Bb*Hh*Nn*Dd];
__device__ uint2  g_qp[CVT_PAIRS];         /* (hi bf16x2, lo bf16x2) */
__device__ uint2  g_kp[CVT_PAIRS];
__device__ float  g_P[(size_t)Bb*Hh*NM];   /* scores -> probs -> mixed attn */
__device__ float  g_X[Bb*Nn*Cc];           /* attn @ V, (b,n,c) */
__device__ double g_stats[16];             /* sum[8], sumsq[8] */
__device__ float  g_st[16];                /* scale[8], shift[8] */

/* ------------------- packed f32x2 FMA helpers --------------------- */
__device__ __forceinline__ unsigned long long f2pk(float lo, float hi){
    unsigned long long r;
    asm("mov.b64 %0, {%1, %2};" : "=l"(r) : "f"(lo), "f"(hi));
    return r;
}
__device__ __forceinline__ void f2fma(unsigned long long& d,
                                      unsigned long long a,
                                      unsigned long long b){
    asm("fma.rn.f32x2 %0, %1, %2, %0;" : "+l"(d) : "l"(a), "l"(b));
}
__device__ __forceinline__ float2 f2up(unsigned long long v){
    float2 r;
    asm("mov.b64 {%0, %1}, %2;" : "=f"(r.x), "=f"(r.y) : "l"(v));
    return r;
}

/* ------------------- warp mma helper ------------------------------ */
__device__ __forceinline__ void mma16816(float* c,
                                         uint32_t a0, uint32_t a1,
                                         uint32_t a2, uint32_t a3,
                                         uint32_t b0, uint32_t b1){
    asm volatile(
        "mma.sync.aligned.m16n8k16.row.col.f32.bf16.bf16.f32 "
        "{%0,%1,%2,%3}, {%4,%5,%6,%7}, {%8,%9}, {%0,%1,%2,%3};"
        : "+f"(c[0]), "+f"(c[1]), "+f"(c[2]), "+f"(c[3])
        : "r"(a0), "r"(a1), "r"(a2), "r"(a3), "r"(b0), "r"(b1));
}

/* K0: zero stats */
__global__ void k_zero(){
    if(threadIdx.x < 16) g_stats[threadIdx.x] = 0.0;
}

/* K1: 3x3 same-pad conv per token; grid (B*N, 3), block 256.
   Q path output is pre-scaled by QK_SCALE. */
__global__ void k_conv(const float* __restrict__ q,
                       const float* __restrict__ kk,
                       const float* __restrict__ vv,
                       const float* __restrict__ Wq,
                       const float* __restrict__ Wk,
                       const float* __restrict__ Wv){
    const int bn = blockIdx.x;
    const int which = blockIdx.y;
    const float* x = (which==0 ? q : (which==1 ? kk : vv)) + (size_t)bn*Cc;
    const float* W = (which==0 ? Wq : (which==1 ? Wk : Wv));
    float* out = (which==0 ? g_qh : (which==1 ? g_kh : g_vh));
    const float post = (which==0 ? QK_SCALE : 1.0f);

    __shared__ float xs[768];
    __shared__ float ws[81];
    const int t = threadIdx.x;
    xs[t]       = x[t];
    xs[t + 256] = x[t + 256];
    xs[t + 512] = x[t + 512];
    if(t < 81) ws[t] = W[t];
    __syncthreads();

    const int i = t >> 4, j = t & 15;
    const int b = bn / Nn, n = bn % Nn;
    #pragma unroll
    for(int o = 0; o < 3; o++){
        float acc = 0.f;
        #pragma unroll
        for(int c = 0; c < 3; c++){
            const float* xp = xs + c*256;
            const float* wp = ws + (o*3 + c)*9;
            #pragma unroll
            for(int di = 0; di < 3; di++){
                int ii = i + di - 1;
                if(ii < 0 || ii > 15) continue;
                #pragma unroll
                for(int dj = 0; dj < 3; dj++){
                    int jj = j + dj - 1;
                    if(jj < 0 || jj > 15) continue;
                    acc = fmaf(wp[di*3 + dj], xp[ii*16 + jj], acc);
                }
            }
        }
        const int idx = o*256 + i*16 + j;
        const int h = idx / Dd, d = idx % Dd;
        out[(((size_t)b*Hh + h)*Nn + n)*Dd + d] = acc * post;
    }
}

/* K1b: convert Q/K fp32 -> interleaved (hi,lo) bf16x2 pairs.
   grid (CVT_PAIRS/256, 2), block 256 */
__global__ __launch_bounds__(256) void k_cvt(){
    const float* __restrict__ src = blockIdx.y ? g_kh : g_qh;
    uint2* __restrict__ dst = blockIdx.y ? g_kp : g_qp;
    const int i = blockIdx.x*256 + threadIdx.x;
    float2 f = *(const float2*)(src + (size_t)i*2);
    __nv_bfloat162 hi = __float22bfloat162_rn(f);
    float2 r;
    r.x = f.x - __bfloat162float(hi.x);
    r.y = f.y - __bfloat162float(hi.y);
    __nv_bfloat162 lo = __float22bfloat162_rn(r);
    uint2 o;
    o.x = *reinterpret_cast<uint32_t*>(&hi);
    o.y = *reinterpret_cast<uint32_t*>(&lo);
    dst[i] = o;
}

/* ------------------------------------------------------------------ */
/* K2: S = Q_scaled K^T via warp mma.sync bf16 hi/lo split.           */
/*   grid (7 m-tiles of 112, 7 n-tiles of 128, 64 bh), 256 threads.   */
/*   warp w computes rows [n0+16w, n0+16w+16) x cols [m0, m0+112).    */
/* ------------------------------------------------------------------ */
__global__ __launch_bounds__(256) void k_qk_mma(){
    const int bh = blockIdx.z;
    const int m0 = blockIdx.x * 112;
    const int n0 = blockIdx.y * 128;
    const int warp = threadIdx.x >> 5, lane = threadIdx.x & 31;
    const int g = lane >> 2, tig = lane & 3;

    const uint2* __restrict__ Qp = g_qp + (size_t)bh*Nn*NPAIR;
    const uint2* __restrict__ Kp = g_kp + (size_t)bh*Nn*NPAIR;
    float* __restrict__ Pg = g_P + (size_t)bh*NM;

    const int row0 = n0 + warp*16 + g;         /* output rows: row0, row0+8 */
    const int ra0 = (row0     < Nn) ? row0     : Nn-1;   /* clamp for loads */
    const int ra1 = (row0 + 8 < Nn) ? row0 + 8 : Nn-1;

    float acc[14][4];
    #pragma unroll
    for(int nf = 0; nf < 14; nf++)
        #pragma unroll
        for(int c = 0; c < 4; c++) acc[nf][c] = 0.f;

    #pragma unroll
    for(int ks = 0; ks < 6; ks++){
        const int p0 = ks*8 + tig;   /* pair index of k=tig*2   */
        const int p1 = p0 + 4;       /* pair index of k=tig*2+8 */
        const uint2 qa = Qp[ra0*NPAIR + p0];
        const uint2 qb = Qp[ra1*NPAIR + p0];
        const uint2 qc = Qp[ra0*NPAIR + p1];
        const uint2 qd = Qp[ra1*NPAIR + p1];
        #pragma unroll
        for(int nf = 0; nf < 14; nf++){
            const int m = m0 + nf*8 + g;
            const uint2 k0 = Kp[m*NPAIR + p0];
            const uint2 k1 = Kp[m*NPAIR + p1];
            /* hi*hi + hi*lo + lo*hi */
            mma16816(acc[nf], qa.x, qb.x, qc.x, qd.x, k0.x, k1.x);
            mma16816(acc[nf], qa.x, qb.x, qc.x, qd.x, k0.y, k1.y);
            mma16816(acc[nf], qa.y, qb.y, qc.y, qd.y, k0.x, k1.x);
        }
    }

    #pragma unroll
    for(int nf = 0; nf < 14; nf++){
        const int m = m0 + nf*8 + tig*2;
        if(row0 < Nn){
            float2 v; v.x = acc[nf][0]; v.y = acc[nf][1];
            *(float2*)(Pg + (size_t)row0*Nn + m) = v;
        }
        if(row0 + 8 < Nn){
            float2 v; v.x = acc[nf][2]; v.y = acc[nf][3];
            *(float2*)(Pg + (size_t)(row0+8)*Nn + m) = v;
        }
    }
}

/* K3: in-place row softmax; grid (64*784), block 256 */
__global__ __launch_bounds__(256) void k_softmax(){
    float* __restrict__ row = g_P + (size_t)blockIdx.x * Nn;
    const int tid = threadIdx.x;
    const int lane = tid & 31, wid = tid >> 5;
    __shared__ float red[8];
    __shared__ float bc;

    float v[4];
    #pragma unroll
    for(int i = 0; i < 4; i++){
        int j = tid + i*256;
        v[i] = (j < Nn) ? row[j] : -1e30f;
    }
    float mx = fmaxf(fmaxf(v[0],v[1]), fmaxf(v[2],v[3]));
    #pragma unroll
    for(int o = 16; o > 0; o >>= 1) mx = fmaxf(mx, __shfl_xor_sync(0xffffffffu, mx, o));
    if(lane == 0) red[wid] = mx;
    __syncthreads();
    if(tid == 0){
        float m = red[0];
        #pragma unroll
        for(int w = 1; w < 8; w++) m = fmaxf(m, red[w]);
        bc = m;
    }
    __syncthreads();
    mx = bc;

    float s = 0.f;
    #pragma unroll
    for(int i = 0; i < 4; i++){
        int j = tid + i*256;
        v[i] = (j < Nn) ? __expf(v[i] - mx) : 0.f;
        s += v[i];
    }
    #pragma unroll
    for(int o = 16; o > 0; o >>= 1) s += __shfl_xor_sync(0xffffffffu, s, o);
    __syncthreads();
    if(lane == 0) red[wid] = s;
    __syncthreads();
    if(tid == 0){
        float t = 0.f;
        #pragma unroll
        for(int w = 0; w < 8; w++) t += red[w];
        bc = 1.f / t;
    }
    __syncthreads();
    float inv = bc;
    #pragma unroll
    for(int i = 0; i < 4; i++){
        int j = tid + i*256;
        if(j < Nn) row[j] = v[i] * inv;
    }
}

/* K4: cross-head mix IN PLACE on g_P + BN stats; grid (2401, 8), block 256 */
__global__ __launch_bounds__(256) void k_mix(const float* __restrict__ Wre,
                                             const float* __restrict__ bre){
    __shared__ float wsh[64];
    __shared__ float bsh[8];
    __shared__ float bsum[16];
    const int tid = threadIdx.x;
    const int lane = tid & 31;
    if(tid < 64) wsh[tid] = Wre[tid];
    if(tid < 8)  bsh[tid] = bre[tid];
    if(tid < 16) bsum[tid] = 0.f;
    __syncthreads();

    const int b = blockIdx.y;
    const size_t idx = (size_t)blockIdx.x*256 + tid;   /* < NM */
    float* __restrict__ Pp = g_P + (size_t)b*Hh*NM + idx;

    float p[8];
    #pragma unroll
    for(int h = 0; h < 8; h++) p[h] = Pp[(size_t)h*NM];

    float ls[8], lq[8];
    float av[8];
    #pragma unroll
    for(int o = 0; o < 8; o++){
        float a = bsh[o];
        #pragma unroll
        for(int h = 0; h < 8; h++) a = fmaf(wsh[o*8+h], p[h], a);
        av[o] = a;
        ls[o] = a;
        lq[o] = a*a;
    }
    #pragma unroll
    for(int o = 0; o < 8; o++) Pp[(size_t)o*NM] = av[o];

    #pragma unroll
    for(int o = 0; o < 8; o++){
        #pragma unroll
        for(int s = 16; s > 0; s >>= 1){
            ls[o] += __shfl_xor_sync(0xffffffffu, ls[o], s);
            lq[o] += __shfl_xor_sync(0xffffffffu, lq[o], s);
        }
    }
    if(lane == 0){
        #pragma unroll
        for(int o = 0; o < 8; o++){
            atomicAdd(&bsum[o],   ls[o]);
            atomicAdd(&bsum[8+o], lq[o]);
        }
    }
    __syncthreads();
    if(tid < 16) atomicAdd(&g_stats[tid], (double)bsum[tid]);
}

/* K5: finalize BN affine */
__global__ void k_bnfin(const float* __restrict__ gamma,
                        const float* __restrict__ beta){
    int o = threadIdx.x;
    if(o < 8){
        double mean = g_stats[o]   / BN_CNT;
        double var  = g_stats[8+o] / BN_CNT - mean*mean;
        float s = gamma[o] * rsqrtf((float)var + 1e-5f);
        g_st[o]   = s;
        g_st[8+o] = beta[o] - (float)mean * s;
    }
}

/* K6: X = BN(A) @ V ; grid (13, 64), block 256; tile 64 rows x 96 cols */
__global__ __launch_bounds__(256) void k_av(){
    const int bh = blockIdx.y;
    const int n0 = blockIdx.x * 64;
    const int o  = bh & 7;
    const int b  = bh >> 3;
    const float s = g_st[o];
    const float t = g_st[8+o];
    const float* __restrict__ Ag = g_P + (size_t)bh*NM;
    const float* __restrict__ Vg = g_vh + (size_t)bh*Nn*Dd;

    __shared__ float As2[64][36];
    __shared__ float Vs[32][100];
    const int tid = threadIdx.x;
    const int tx = tid & 15, ty = tid >> 4;

    unsigned long long acc[4][3];
    #pragma unroll
    for(int i=0;i<4;i++)
        #pragma unroll
        for(int j=0;j<3;j++) acc[i][j]=0ULL;

    for(int mc = 0; mc < Nn; mc += 32){
        #pragma unroll
        for(int it = 0; it < 2; it++){
            int idx = tid + it*256;
            int r = idx >> 3, kq = idx & 7;
            int m = mc + kq*4;
            float4 va = make_float4(0.f,0.f,0.f,0.f);
            if(n0 + r < Nn && m + 3 < Nn){
                float4 raw = *(const float4*)(Ag + (size_t)(n0+r)*Nn + m);
                va.x = fmaf(raw.x, s, t);
                va.y = fmaf(raw.y, s, t);
                va.z = fmaf(raw.z, s, t);
                va.w = fmaf(raw.w, s, t);
            }
            *(float4*)&As2[r][kq*4] = va;
        }
        #pragma unroll
        for(int it = 0; it < 3; it++){
            int idx = tid + it*256;
            int r = idx / 24, dq = idx % 24;
            float4 vv = make_float4(0.f,0.f,0.f,0.f);
            if(mc + r < Nn) vv = *(const float4*)(Vg + (size_t)(mc+r)*Dd + dq*4);
            *(float4*)&Vs[r][dq*4] = vv;
        }
        __syncthreads();
        #pragma unroll 4
        for(int k = 0; k < 32; k++){
            float2 b0 = *(const float2*)&Vs[k][tx*6];
            float2 b1 = *(const float2*)&Vs[k][tx*6+2];
            float2 b2 = *(const float2*)&Vs[k][tx*6+4];
            unsigned long long bp0 = f2pk(b0.x,b0.y);
            unsigned long long bp1 = f2pk(b1.x,b1.y);
            unsigned long long bp2 = f2pk(b2.x,b2.y);
            #pragma unroll
            for(int i = 0; i < 4; i++){
                float a = As2[ty*4+i][k];
                unsigned long long ad = f2pk(a, a);
                f2fma(acc[i][0], ad, bp0);
                f2fma(acc[i][1], ad, bp1);
                f2fma(acc[i][2], ad, bp2);
            }
        }
        __syncthreads();
    }

    #pragma unroll
    for(int i = 0; i < 4; i++){
        int n = n0 + ty*4 + i;
        if(n >= Nn) continue;
        float* outp = g_X + ((size_t)(b*Nn + n))*Cc + o*Dd + tx*6;
        #pragma unroll
        for(int j = 0; j < 3; j++){
            float2 v = f2up(acc[i][j]);
            outp[j*2]   = v.x;
            outp[j*2+1] = v.y;
        }
    }
}

/* K7: out = X @ Wp^T + bp ; grid (6, 49), block 256, 128x128 tile */
__global__ __launch_bounds__(256) void k_proj(float* __restrict__ out,
                                              const float* __restrict__ Wp,
                                              const float* __restrict__ bp){
    const int c0 = blockIdx.x*128, n0 = blockIdx.y*128;
    const float* __restrict__ Ag = g_X;
    __shared__ float As[16][132];
    __shared__ float Bs[16][132];
    const int tid = threadIdx.x;
    const int tx = tid & 15, ty = tid >> 4;

    unsigned long long acc[8][4];
    #pragma unroll
    for(int r=0;r<8;r++)
        #pragma unroll
        for(int c=0;c<4;c++) acc[r][c]=0ULL;

    for(int k0 = 0; k0 < Cc; k0 += 16){
        #pragma unroll
        for(int it = 0; it < 2; it++){
            int idx = tid + it*256;
            int r = idx >> 2, kq = idx & 3;
            float4 va = *(const float4*)(Ag + (size_t)(n0+r)*Cc + k0 + kq*4);
            float4 vb = *(const float4*)(Wp + (size_t)(c0+r)*Cc + k0 + kq*4);
            As[kq*4+0][r]=va.x; As[kq*4+1][r]=va.y; As[kq*4+2][r]=va.z; As[kq*4+3][r]=va.w;
            Bs[kq*4+0][r]=vb.x; Bs[kq*4+1][r]=vb.y; Bs[kq*4+2][r]=vb.z; Bs[kq*4+3][r]=vb.w;
        }
        __syncthreads();
        #pragma unroll
        for(int k = 0; k < 16; k++){
            float4 a0 = *(const float4*)&As[k][ty*8];
            float4 a1 = *(const float4*)&As[k][ty*8+4];
            float4 b0 = *(const float4*)&Bs[k][tx*8];
            float4 b1 = *(const float4*)&Bs[k][tx*8+4];
            unsigned long long bp0 = f2pk(b0.x,b0.y), bp1 = f2pk(b0.z,b0.w);
            unsigned long long bp2 = f2pk(b1.x,b1.y), bp3 = f2pk(b1.z,b1.w);
            float av[8] = {a0.x,a0.y,a0.z,a0.w,a1.x,a1.y,a1.z,a1.w};
            #pragma unroll
            for(int r = 0; r < 8; r++){
                unsigned long long ad = f2pk(av[r], av[r]);
                f2fma(acc[r][0], ad, bp0);
                f2fma(acc[r][1], ad, bp1);
                f2fma(acc[r][2], ad, bp2);
                f2fma(acc[r][3], ad, bp3);
            }
        }
        __syncthreads();
    }

    #pragma unroll
    for(int r = 0; r < 8; r++){
        int n = n0 + ty*8 + r;
        #pragma unroll
        for(int c = 0; c < 4; c++){
            float2 v = f2up(acc[r][c]);
            int cc = c0 + tx*8 + c*2;
            out[(size_t)n*Cc + cc]   = v.x + bp[cc];
            out[(size_t)n*Cc + cc+1] = v.y + bp[cc+1];
        }
    }
}

extern "C" void kernel_launch(void* const* d_in, const int* in_sizes, int n_in,
                              void* d_out, int out_size){
    const float* q    = (const float*)d_in[0];
    const float* k    = (const float*)d_in[1];
    const float* v    = (const float*)d_in[2];
    const float* Wq   = (const float*)d_in[3];
    const float* Wk   = (const float*)d_in[4];
    const float* Wv   = (const float*)d_in[5];
    const float* Wre  = (const float*)d_in[6];
    const float* bre  = (const float*)d_in[7];
    const float* gma  = (const float*)d_in[8];
    const float* beta = (const float*)d_in[9];
    const float* Wp   = (const float*)d_in[10];
    const float* bp   = (const float*)d_in[11];
    float* out = (float*)d_out;

    k_zero<<<1, 32>>>();
    k_conv<<<dim3(Bb*Nn, 3), 256>>>(q, k, v, Wq, Wk, Wv);
    k_cvt<<<dim3(CVT_PAIRS/256, 2), 256>>>();
    k_qk_mma<<<dim3(7, 7, Bb*Hh), 256>>>();
    k_softmax<<<Bb*Hh*Nn, 256>>>();
    k_mix<<<dim3(NM/256, Bb), 256>>>(Wre, bre);
    k_bnfin<<<1, 32>>>(gma, beta);
    k_av<<<dim3(13, Bb*Hh), 256>>>();
    k_proj<<<dim3(6, 49), 256>>>(out, Wp, bp);
}

// round 8
// speedup vs baseline: 1.2972x; 1.1950x over previous
#include <cuda_runtime.h>
#include <cuda_bf16.h>
#include <cstdint>
#include <math.h>

#define Bb 8
#define Nn 784
#define Cc 768
#define Hh 8
#define Dd 96
#define NM 614656               /* 784*784 */
#define NMP 307328              /* NM/2 pairs */
#define VP 392                  /* pairs per V column (784/2) */
#define QK_SCALE 0.10206207261596577f  /* 96^-0.5 */
#define BN_CNT 4917248.0        /* B*NM */
#define NPAIR 48                /* bf16 pairs per head row (96/2) */
#define CVT_PAIRS (Bb*Hh*Nn*NPAIR)   /* 2408448 */

/* ------------- static scratch (no allocation allowed) ------------- */
__device__ float  g_qh[Bb*Hh*Nn*Dd];
__device__ float  g_kh[Bb*Hh*Nn*Dd];
__device__ float  g_vh[Bb*Hh*Nn*Dd];
__device__ uint2  g_qp[CVT_PAIRS];         /* (hi bf16x2, lo bf16x2) */
__device__ uint2  g_kp[CVT_PAIRS];
__device__ uint2  g_vp[Bb*Hh*Dd*VP];       /* V transposed+packed */
__device__ float  g_vcs[Bb*Hh*Dd];         /* per-(bh,d) column sums of V */
__device__ float  g_P[(size_t)Bb*Hh*NM];   /* scores->probs->packed mixed A */
__device__ float  g_X[Bb*Nn*Cc];           /* attn @ V, (b,n,c) */
__device__ double g_stats[16];             /* sum[8], sumsq[8] */
__device__ float  g_st[16];                /* scale[8], shift[8] */

/* ------------------- packed f32x2 FMA helpers --------------------- */
__device__ __forceinline__ unsigned long long f2pk(float lo, float hi){
    unsigned long long r;
    asm("mov.b64 %0, {%1, %2};" : "=l"(r) : "f"(lo), "f"(hi));
    return r;
}
__device__ __forceinline__ void f2fma(unsigned long long& d,
                                      unsigned long long a,
                                      unsigned long long b){
    asm("fma.rn.f32x2 %0, %1, %2, %0;" : "+l"(d) : "l"(a), "l"(b));
}
__device__ __forceinline__ float2 f2up(unsigned long long v){
    float2 r;
    asm("mov.b64 {%0, %1}, %2;" : "=f"(r.x), "=f"(r.y) : "l"(v));
    return r;
}

/* ------------------- warp mma helper ------------------------------ */
__device__ __forceinline__ void mma16816(float* c,
                                         uint32_t a0, uint32_t a1,
                                         uint32_t a2, uint32_t a3,
                                         uint32_t b0, uint32_t b1){
    asm volatile(
        "mma.sync.aligned.m16n8k16.row.col.f32.bf16.bf16.f32 "
        "{%0,%1,%2,%3}, {%4,%5,%6,%7}, {%8,%9}, {%0,%1,%2,%3};"
        : "+f"(c[0]), "+f"(c[1]), "+f"(c[2]), "+f"(c[3])
        : "r"(a0), "r"(a1), "r"(a2), "r"(a3), "r"(b0), "r"(b1));
}

/* K0: zero stats */
__global__ void k_zero(){
    if(threadIdx.x < 16) g_stats[threadIdx.x] = 0.0;
}

/* K1: 3x3 same-pad conv per token; grid (B*N, 3), block 256.
   Q path output is pre-scaled by QK_SCALE. */
__global__ void k_conv(const float* __restrict__ q,
                       const float* __restrict__ kk,
                       const float* __restrict__ vv,
                       const float* __restrict__ Wq,
                       const float* __restrict__ Wk,
                       const float* __restrict__ Wv){
    const int bn = blockIdx.x;
    const int which = blockIdx.y;
    const float* x = (which==0 ? q : (which==1 ? kk : vv)) + (size_t)bn*Cc;
    const float* W = (which==0 ? Wq : (which==1 ? Wk : Wv));
    float* out = (which==0 ? g_qh : (which==1 ? g_kh : g_vh));
    const float post = (which==0 ? QK_SCALE : 1.0f);

    __shared__ float xs[768];
    __shared__ float ws[81];
    const int t = threadIdx.x;
    xs[t]       = x[t];
    xs[t + 256] = x[t + 256];
    xs[t + 512] = x[t + 512];
    if(t < 81) ws[t] = W[t];
    __syncthreads();

    const int i = t >> 4, j = t & 15;
    const int b = bn / Nn, n = bn % Nn;
    #pragma unroll
    for(int o = 0; o < 3; o++){
        float acc = 0.f;
        #pragma unroll
        for(int c = 0; c < 3; c++){
            const float* xp = xs + c*256;
            const float* wp = ws + (o*3 + c)*9;
            #pragma unroll
            for(int di = 0; di < 3; di++){
                int ii = i + di - 1;
                if(ii < 0 || ii > 15) continue;
                #pragma unroll
                for(int dj = 0; dj < 3; dj++){
                    int jj = j + dj - 1;
                    if(jj < 0 || jj > 15) continue;
                    acc = fmaf(wp[di*3 + dj], xp[ii*16 + jj], acc);
                }
            }
        }
        const int idx = o*256 + i*16 + j;
        const int h = idx / Dd, d = idx % Dd;
        out[(((size_t)b*Hh + h)*Nn + n)*Dd + d] = acc * post;
    }
}

/* K1b: convert Q/K fp32 -> interleaved (hi,lo) bf16x2 pairs.
   grid (CVT_PAIRS/256, 2), block 256 */
__global__ __launch_bounds__(256) void k_cvt(){
    const float* __restrict__ src = blockIdx.y ? g_kh : g_qh;
    uint2* __restrict__ dst = blockIdx.y ? g_kp : g_qp;
    const int i = blockIdx.x*256 + threadIdx.x;
    float2 f = *(const float2*)(src + (size_t)i*2);
    __nv_bfloat162 hi = __float22bfloat162_rn(f);
    float2 r;
    r.x = f.x - __bfloat162float(hi.x);
    r.y = f.y - __bfloat162float(hi.y);
    __nv_bfloat162 lo = __float22bfloat162_rn(r);
    uint2 o;
    o.x = *reinterpret_cast<uint32_t*>(&hi);
    o.y = *reinterpret_cast<uint32_t*>(&lo);
    dst[i] = o;
}

/* K1c: transpose+pack V into g_vp[bh][d][pair]; grid (64, 13), block 256 */
__global__ __launch_bounds__(256) void k_vt(){
    __shared__ float vtile[64][96];
    const int bh = blockIdx.x, t = blockIdx.y;
    const int m0 = t*64;
    const int tid = threadIdx.x;
    const float* __restrict__ Vg = g_vh + (size_t)bh*Nn*Dd;
    for(int idx = tid; idx < 64*96; idx += 256){
        int ml = idx / 96, d = idx % 96;
        int m = m0 + ml;
        vtile[ml][d] = (m < Nn) ? Vg[(size_t)m*Dd + d] : 0.f;
    }
    __syncthreads();
    for(int idx = tid; idx < 96*32; idx += 256){
        int d = idx >> 5, pl = idx & 31;
        int p = t*32 + pl;
        if(p < VP){
            float2 f;
            f.x = vtile[pl*2][d];
            f.y = vtile[pl*2+1][d];
            __nv_bfloat162 hi = __float22bfloat162_rn(f);
            float2 r;
            r.x = f.x - __bfloat162float(hi.x);
            r.y = f.y - __bfloat162float(hi.y);
            __nv_bfloat162 lo = __float22bfloat162_rn(r);
            uint2 o;
            o.x = *reinterpret_cast<uint32_t*>(&hi);
            o.y = *reinterpret_cast<uint32_t*>(&lo);
            g_vp[((size_t)bh*Dd + d)*VP + p] = o;
        }
    }
}

/* K1d: V column sums; grid 64, block 128 */
__global__ void k_vsum(){
    const int bh = blockIdx.x, d = threadIdx.x;
    if(d < Dd){
        const float* __restrict__ Vg = g_vh + (size_t)bh*Nn*Dd;
        float s = 0.f;
        for(int m = 0; m < Nn; m++) s += Vg[(size_t)m*Dd + d];
        g_vcs[bh*Dd + d] = s;
    }
}

/* ------------------------------------------------------------------ */
/* K2: S = Q_scaled K^T via warp mma.sync bf16 hi/lo split, smem K.   */
/*   grid (7 m-tiles of 112, 7 n-tiles of 128, 64 bh), 256 threads.   */
/* ------------------------------------------------------------------ */
__global__ __launch_bounds__(256) void k_qk_mma(){
    __shared__ uint2 ksm[48][116];   /* [pair][row]; 116*2 words ≡ 8 mod 32 */
    const int bh = blockIdx.z;
    const int m0 = blockIdx.x * 112;
    const int n0 = blockIdx.y * 128;
    const int tid = threadIdx.x;
    const int warp = tid >> 5, lane = tid & 31;
    const int g = lane >> 2, tig = lane & 3;

    const uint2* __restrict__ Qp = g_qp + (size_t)bh*Nn*NPAIR;
    const uint2* __restrict__ Kp = g_kp + (size_t)bh*Nn*NPAIR;
    float* __restrict__ Pg = g_P + (size_t)bh*NM;

    /* cooperative K tile load (rows m0..m0+111 always in range: 7*112=784) */
    for(int idx = tid; idx < 112*48; idx += 256){
        int row = idx / 48, p = idx % 48;
        ksm[p][row] = Kp[(size_t)(m0+row)*NPAIR + p];
    }
    __syncthreads();

    const int row0 = n0 + warp*16 + g;
    const int ra0 = (row0     < Nn) ? row0     : Nn-1;
    const int ra1 = (row0 + 8 < Nn) ? row0 + 8 : Nn-1;

    float acc[14][4];
    #pragma unroll
    for(int nf = 0; nf < 14; nf++)
        #pragma unroll
        for(int c = 0; c < 4; c++) acc[nf][c] = 0.f;

    #pragma unroll
    for(int ks = 0; ks < 6; ks++){
        const int p0 = ks*8 + tig, p1 = p0 + 4;
        const uint2 qa = Qp[(size_t)ra0*NPAIR + p0];
        const uint2 qb = Qp[(size_t)ra1*NPAIR + p0];
        const uint2 qc = Qp[(size_t)ra0*NPAIR + p1];
        const uint2 qd = Qp[(size_t)ra1*NPAIR + p1];
        #pragma unroll
        for(int nf = 0; nf < 14; nf++){
            const int ml = nf*8 + g;
            const uint2 k0 = ksm[p0][ml];
            const uint2 k1 = ksm[p1][ml];
            mma16816(acc[nf], qa.x, qb.x, qc.x, qd.x, k0.x, k1.x);
            mma16816(acc[nf], qa.x, qb.x, qc.x, qd.x, k0.y, k1.y);
            mma16816(acc[nf], qa.y, qb.y, qc.y, qd.y, k0.x, k1.x);
        }
    }

    #pragma unroll
    for(int nf = 0; nf < 14; nf++){
        const int m = m0 + nf*8 + tig*2;
        if(row0 < Nn){
            float2 v; v.x = acc[nf][0]; v.y = acc[nf][1];
            *(float2*)(Pg + (size_t)row0*Nn + m) = v;
        }
        if(row0 + 8 < Nn){
            float2 v; v.x = acc[nf][2]; v.y = acc[nf][3];
            *(float2*)(Pg + (size_t)(row0+8)*Nn + m) = v;
        }
    }
}

/* K3: in-place row softmax; grid (64*784), block 256 */
__global__ __launch_bounds__(256) void k_softmax(){
    float* __restrict__ row = g_P + (size_t)blockIdx.x * Nn;
    const int tid = threadIdx.x;
    const int lane = tid & 31, wid = tid >> 5;
    __shared__ float red[8];
    __shared__ float bc;

    float v[4];
    #pragma unroll
    for(int i = 0; i < 4; i++){
        int j = tid + i*256;
        v[i] = (j < Nn) ? row[j] : -1e30f;
    }
    float mx = fmaxf(fmaxf(v[0],v[1]), fmaxf(v[2],v[3]));
    #pragma unroll
    for(int o = 16; o > 0; o >>= 1) mx = fmaxf(mx, __shfl_xor_sync(0xffffffffu, mx, o));
    if(lane == 0) red[wid] = mx;
    __syncthreads();
    if(tid == 0){
        float m = red[0];
        #pragma unroll
        for(int w = 1; w < 8; w++) m = fmaxf(m, red[w]);
        bc = m;
    }
    __syncthreads();
    mx = bc;

    float s = 0.f;
    #pragma unroll
    for(int i = 0; i < 4; i++){
        int j = tid + i*256;
        v[i] = (j < Nn) ? __expf(v[i] - mx) : 0.f;
        s += v[i];
    }
    #pragma unroll
    for(int o = 16; o > 0; o >>= 1) s += __shfl_xor_sync(0xffffffffu, s, o);
    __syncthreads();
    if(lane == 0) red[wid] = s;
    __syncthreads();
    if(tid == 0){
        float t = 0.f;
        #pragma unroll
        for(int w = 0; w < 8; w++) t += red[w];
        bc = 1.f / t;
    }
    __syncthreads();
    float inv = bc;
    #pragma unroll
    for(int i = 0; i < 4; i++){
        int j = tid + i*256;
        if(j < Nn) row[j] = v[i] * inv;
    }
}

/* K4: cross-head mix IN PLACE, output packed hi/lo bf16x2 pairs + BN
   stats; grid (1201, 8), block 256; each thread handles one m-pair. */
__global__ __launch_bounds__(256) void k_mix(const float* __restrict__ Wre,
                                             const float* __restrict__ bre){
    __shared__ float wsh[64];
    __shared__ float bsh[8];
    __shared__ float bsum[16];
    const int tid = threadIdx.x;
    const int lane = tid & 31;
    if(tid < 64) wsh[tid] = Wre[tid];
    if(tid < 8)  bsh[tid] = bre[tid];
    if(tid < 16) bsum[tid] = 0.f;
    __syncthreads();

    const int b = blockIdx.y;
    const int i = blockIdx.x*256 + tid;
    const bool act = (i < NMP);
    float2* __restrict__ Pp = (float2*)(g_P + (size_t)b*Hh*NM) + i;

    float2 p2[8];
    if(act){
        #pragma unroll
        for(int h = 0; h < 8; h++) p2[h] = Pp[(size_t)h*NMP];
    }

    float ls[8], lq[8];
    #pragma unroll
    for(int o = 0; o < 8; o++){
        if(act){
            float ax = bsh[o], ay = bsh[o];
            #pragma unroll
            for(int h = 0; h < 8; h++){
                ax = fmaf(wsh[o*8+h], p2[h].x, ax);
                ay = fmaf(wsh[o*8+h], p2[h].y, ay);
            }
            float2 f; f.x = ax; f.y = ay;
            __nv_bfloat162 hi = __float22bfloat162_rn(f);
            float2 r;
            r.x = ax - __bfloat162float(hi.x);
            r.y = ay - __bfloat162float(hi.y);
            __nv_bfloat162 lo = __float22bfloat162_rn(r);
            uint2 pk;
            pk.x = *reinterpret_cast<uint32_t*>(&hi);
            pk.y = *reinterpret_cast<uint32_t*>(&lo);
            *(uint2*)&Pp[(size_t)o*NMP] = pk;
            ls[o] = ax + ay;
            lq[o] = ax*ax + ay*ay;
        }else{
            ls[o] = 0.f; lq[o] = 0.f;
        }
    }

    #pragma unroll
    for(int o = 0; o < 8; o++){
        #pragma unroll
        for(int s = 16; s > 0; s >>= 1){
            ls[o] += __shfl_xor_sync(0xffffffffu, ls[o], s);
            lq[o] += __shfl_xor_sync(0xffffffffu, lq[o], s);
        }
    }
    if(lane == 0){
        #pragma unroll
        for(int o = 0; o < 8; o++){
            atomicAdd(&bsum[o],   ls[o]);
            atomicAdd(&bsum[8+o], lq[o]);
        }
    }
    __syncthreads();
    if(tid < 16) atomicAdd(&g_stats[tid], (double)bsum[tid]);
}

/* K5: finalize BN affine */
__global__ void k_bnfin(const float* __restrict__ gamma,
                        const float* __restrict__ beta){
    int o = threadIdx.x;
    if(o < 8){
        double mean = g_stats[o]   / BN_CNT;
        double var  = g_stats[8+o] / BN_CNT - mean*mean;
        float s = gamma[o] * rsqrtf((float)var + 1e-5f);
        g_st[o]   = s;
        g_st[8+o] = beta[o] - (float)mean * s;
    }
}

/* ------------------------------------------------------------------ */
/* K6: X = s*(A@V) + t*colsumV via warp mma.sync, smem-chunked V.     */
/*   grid (7 row-tiles of 128, 64 bh), 256 threads.                   */
/* ------------------------------------------------------------------ */
__global__ __launch_bounds__(256) void k_av_mma(){
    __shared__ uint2 vsm[56][100];   /* [pair][d]; 100*2 words ≡ 8 mod 32 */
    const int bh = blockIdx.y;
    const int n0 = blockIdx.x * 128;
    const int o  = bh & 7;
    const int b  = bh >> 3;
    const int tid = threadIdx.x;
    const int warp = tid >> 5, lane = tid & 31;
    const int g = lane >> 2, tig = lane & 3;

    const uint2* __restrict__ Ap = (const uint2*)g_P + (size_t)bh*NMP;
    const uint2* __restrict__ Vp = g_vp + (size_t)bh*Dd*VP;

    const int row0 = n0 + warp*16 + g;
    const int ra0 = (row0     < Nn) ? row0     : Nn-1;
    const int ra1 = (row0 + 8 < Nn) ? row0 + 8 : Nn-1;

    float acc[12][4];
    #pragma unroll
    for(int nf = 0; nf < 12; nf++)
        #pragma unroll
        for(int c = 0; c < 4; c++) acc[nf][c] = 0.f;

    for(int ch = 0; ch < 7; ch++){
        const int pb = ch*56;
        for(int idx = tid; idx < 56*96; idx += 256){
            int d = idx / 56, pl = idx % 56;
            vsm[pl][d] = Vp[(size_t)d*VP + pb + pl];
        }
        __syncthreads();

        #pragma unroll
        for(int i = 0; i < 7; i++){
            const int p0l = i*8 + tig, p1l = p0l + 4;
            const uint2 qa = Ap[(size_t)ra0*VP + pb + p0l];
            const uint2 qb = Ap[(size_t)ra1*VP + pb + p0l];
            const uint2 qc = Ap[(size_t)ra0*VP + pb + p1l];
            const uint2 qd = Ap[(size_t)ra1*VP + pb + p1l];
            #pragma unroll
            for(int nf = 0; nf < 12; nf++){
                const int d = nf*8 + g;
                const uint2 v0 = vsm[p0l][d];
                const uint2 v1 = vsm[p1l][d];
                mma16816(acc[nf], qa.x, qb.x, qc.x, qd.x, v0.x, v1.x);
                mma16816(acc[nf], qa.x, qb.x, qc.x, qd.x, v0.y, v1.y);
                mma16816(acc[nf], qa.y, qb.y, qc.y, qd.y, v0.x, v1.x);
            }
        }
        __syncthreads();
    }

    const float s = g_st[o];
    const float t = g_st[8+o];
    #pragma unroll
    for(int nf = 0; nf < 12; nf++){
        const int d0 = nf*8 + tig*2;
        const float cs0 = g_vcs[bh*Dd + d0];
        const float cs1 = g_vcs[bh*Dd + d0 + 1];
        if(row0 < Nn){
            float2 v;
            v.x = fmaf(s, acc[nf][0], t*cs0);
            v.y = fmaf(s, acc[nf][1], t*cs1);
            *(float2*)(g_X + ((size_t)(b*Nn + row0))*Cc + o*Dd + d0) = v;
        }
        if(row0 + 8 < Nn){
            float2 v;
            v.x = fmaf(s, acc[nf][2], t*cs0);
            v.y = fmaf(s, acc[nf][3], t*cs1);
            *(float2*)(g_X + ((size_t)(b*Nn + row0 + 8))*Cc + o*Dd + d0) = v;
        }
    }
}

/* K7: out = X @ Wp^T + bp ; grid (6, 49), block 256, 128x128 tile */
__global__ __launch_bounds__(256) void k_proj(float* __restrict__ out,
                                              const float* __restrict__ Wp,
                                              const float* __restrict__ bp){
    const int c0 = blockIdx.x*128, n0 = blockIdx.y*128;
    const float* __restrict__ Ag = g_X;
    __shared__ float As[16][132];
    __shared__ float Bs[16][132];
    const int tid = threadIdx.x;
    const int tx = tid & 15, ty = tid >> 4;

    unsigned long long acc[8][4];
    #pragma unroll
    for(int r=0;r<8;r++)
        #pragma unroll
        for(int c=0;c<4;c++) acc[r][c]=0ULL;

    for(int k0 = 0; k0 < Cc; k0 += 16){
        #pragma unroll
        for(int it = 0; it < 2; it++){
            int idx = tid + it*256;
            int r = idx >> 2, kq = idx & 3;
            float4 va = *(const float4*)(Ag + (size_t)(n0+r)*Cc + k0 + kq*4);
            float4 vb = *(const float4*)(Wp + (size_t)(c0+r)*Cc + k0 + kq*4);
            As[kq*4+0][r]=va.x; As[kq*4+1][r]=va.y; As[kq*4+2][r]=va.z; As[kq*4+3][r]=va.w;
            Bs[kq*4+0][r]=vb.x; Bs[kq*4+1][r]=vb.y; Bs[kq*4+2][r]=vb.z; Bs[kq*4+3][r]=vb.w;
        }
        __syncthreads();
        #pragma unroll
        for(int k = 0; k < 16; k++){
            float4 a0 = *(const float4*)&As[k][ty*8];
            float4 a1 = *(const float4*)&As[k][ty*8+4];
            float4 b0 = *(const float4*)&Bs[k][tx*8];
            float4 b1 = *(const float4*)&Bs[k][tx*8+4];
            unsigned long long bp0 = f2pk(b0.x,b0.y), bp1 = f2pk(b0.z,b0.w);
            unsigned long long bp2 = f2pk(b1.x,b1.y), bp3 = f2pk(b1.z,b1.w);
            float av[8] = {a0.x,a0.y,a0.z,a0.w,a1.x,a1.y,a1.z,a1.w};
            #pragma unroll
            for(int r = 0; r < 8; r++){
                unsigned long long ad = f2pk(av[r], av[r]);
                f2fma(acc[r][0], ad, bp0);
                f2fma(acc[r][1], ad, bp1);
                f2fma(acc[r][2], ad, bp2);
                f2fma(acc[r][3], ad, bp3);
            }
        }
        __syncthreads();
    }

    #pragma unroll
    for(int r = 0; r < 8; r++){
        int n = n0 + ty*8 + r;
        #pragma unroll
        for(int c = 0; c < 4; c++){
            float2 v = f2up(acc[r][c]);
            int cc = c0 + tx*8 + c*2;
            out[(size_t)n*Cc + cc]   = v.x + bp[cc];
            out[(size_t)n*Cc + cc+1] = v.y + bp[cc+1];
        }
    }
}

extern "C" void kernel_launch(void* const* d_in, const int* in_sizes, int n_in,
                              void* d_out, int out_size){
    const float* q    = (const float*)d_in[0];
    const float* k    = (const float*)d_in[1];
    const float* v    = (const float*)d_in[2];
    const float* Wq   = (const float*)d_in[3];
    const float* Wk   = (const float*)d_in[4];
    const float* Wv   = (const float*)d_in[5];
    const float* Wre  = (const float*)d_in[6];
    const float* bre  = (const float*)d_in[7];
    const float* gma  = (const float*)d_in[8];
    const float* beta = (const float*)d_in[9];
    const float* Wp   = (const float*)d_in[10];
    const float* bp   = (const float*)d_in[11];
    float* out = (float*)d_out;

    k_zero<<<1, 32>>>();
    k_conv<<<dim3(Bb*Nn, 3), 256>>>(q, k, v, Wq, Wk, Wv);
    k_cvt<<<dim3(CVT_PAIRS/256, 2), 256>>>();
    k_vt<<<dim3(Bb*Hh, 13), 256>>>();
    k_vsum<<<Bb*Hh, 128>>>();
    k_qk_mma<<<dim3(7, 7, Bb*Hh), 256>>>();
    k_softmax<<<Bb*Hh*Nn, 256>>>();
    k_mix<<<dim3((NMP + 255)/256, Bb), 256>>>(Wre, bre);
    k_bnfin<<<1, 32>>>(gma, beta);
    k_av_mma<<<dim3(7, Bb*Hh), 256>>>();
    k_proj<<<dim3(6, 49), 256>>>(out, Wp, bp);
}